// round 5
// baseline (speedup 1.0000x reference)
#include <cuda_runtime.h>

// CliffordInteractionExpert: B=8, T=4096, D=1024, ALG=16 (metric 3,1,0)
// out = x + gate * sum_{shift in 1,2,4} delta_shift, c = x - roll(x, shift)
//   bivector lanes {3,5,6,9,10,12} per 16-chunk: sb*(x_i c_j - x_j c_i),
//     (i,j) in {(1,2),(1,4),(2,4),(1,8),(2,8),(4,8)}  (all canonical +1)
//   D-index 0 gets ss * sum_{chunks,i} d_i x_i c_i  (C0 is diagonal)
//   gate = sigmoid(x . gate_w + gate_b)   (loop invariant)

#define T_DIM 4096
#define D_DIM 1024
#define TILE 16
#define HALO 4
#define ROWS (TILE + HALO)   // 20
#define THREADS 512
#define ROW_F4 256           // float4 per row (1024 floats)

// Bank-conflict-free smem slot for (chunk c in 0..63, quad q in 0..3):
// read side (lane l -> chunk l): granule (l ^ 2q) & 7 distinct per octet;
// store side (coalesced f = 4c+q): granule (c ^ 2q) & 7 distinct per octet.
__device__ __forceinline__ int swz(int c, int q) { return (q << 6) + (c ^ (q << 1)); }

__global__ void __launch_bounds__(THREADS, 2)
clifford_kernel(const float* __restrict__ x,
                const float* __restrict__ gate_w,
                const float* __restrict__ gate_b,
                const float* __restrict__ sw_p,
                const float* __restrict__ bw_p,
                float* __restrict__ out)
{
    extern __shared__ float4 sm4[];   // ROWS * 256 float4 = 80 KB
    const int tid = threadIdx.x;
    const int b = blockIdx.y;
    const int t0 = blockIdx.x * TILE;

    // ---- cooperative coalesced load of rows [t0-4, t0+16) (circular) ----
    const float4* xg = (const float4*)x + (size_t)b * T_DIM * ROW_F4;
    #pragma unroll
    for (int it = 0; it < (ROWS * ROW_F4) / THREADS; ++it) {
        int idx = it * THREADS + tid;
        int r = idx >> 8;          // row 0..19
        int f = idx & 255;         // float4 within row
        int g = (t0 + r - HALO) & (T_DIM - 1);
        sm4[r * ROW_F4 + swz(f >> 2, f & 3)] = xg[(size_t)g * ROW_F4 + f];
    }
    __syncthreads();

    const int w = tid >> 5;        // warp == token within tile
    const int lane = tid & 31;
    const int lr = w + HALO;       // this token's smem row

    float wacc[2][6];
    #pragma unroll
    for (int ch = 0; ch < 2; ++ch)
        #pragma unroll
        for (int k = 0; k < 6; ++k) wacc[ch][k] = 0.f;
    float scal = 0.f, gdot = 0.f;

    #pragma unroll
    for (int ch = 0; ch < 2; ++ch) {
        const int c = lane + (ch << 5);
        float xv[16];
        #pragma unroll
        for (int q = 0; q < 4; ++q) {
            float4 v = sm4[lr * ROW_F4 + swz(c, q)];
            xv[4*q+0] = v.x; xv[4*q+1] = v.y; xv[4*q+2] = v.z; xv[4*q+3] = v.w;
            float4 gw = __ldg((const float4*)gate_w + (c << 2) + q);
            gdot += v.x*gw.x + v.y*gw.y + v.z*gw.z + v.w*gw.w;
        }
        #pragma unroll
        for (int si = 0; si < 3; ++si) {
            const int sh = (si == 2) ? 4 : (si + 1);   // shifts 1,2,4
            const int sr = lr - sh;
            float c1, c2, c4, c8;
            {
                float4 v = sm4[sr * ROW_F4 + swz(c, 0)];
                float d0 = xv[0]-v.x, d1 = xv[1]-v.y, d2 = xv[2]-v.z, d3 = xv[3]-v.w;
                scal += xv[0]*d0 + xv[1]*d1 + xv[2]*d2 - xv[3]*d3;
                c1 = d1; c2 = d2;
            }
            {
                float4 v = sm4[sr * ROW_F4 + swz(c, 1)];
                float d4 = xv[4]-v.x, d5 = xv[5]-v.y, d6 = xv[6]-v.z, d7 = xv[7]-v.w;
                scal += xv[4]*d4 - xv[5]*d5 - xv[6]*d6 - xv[7]*d7;
                c4 = d4;
            }
            {
                float4 v = sm4[sr * ROW_F4 + swz(c, 2)];
                float d8 = xv[8]-v.x, d9 = xv[9]-v.y, d10 = xv[10]-v.z, d11 = xv[11]-v.w;
                scal += -xv[8]*d8 + xv[9]*d9 + xv[10]*d10 + xv[11]*d11;
                c8 = d8;
            }
            {
                float4 v = sm4[sr * ROW_F4 + swz(c, 3)];
                float d12 = xv[12]-v.x, d13 = xv[13]-v.y, d14 = xv[14]-v.z, d15 = xv[15]-v.w;
                scal += xv[12]*d12 + xv[13]*d13 + xv[14]*d14 - xv[15]*d15;
            }
            wacc[ch][0] += xv[1]*c2 - xv[2]*c1;   // -> lane 3
            wacc[ch][1] += xv[1]*c4 - xv[4]*c1;   // -> lane 5
            wacc[ch][2] += xv[2]*c4 - xv[4]*c2;   // -> lane 6
            wacc[ch][3] += xv[1]*c8 - xv[8]*c1;   // -> lane 9
            wacc[ch][4] += xv[2]*c8 - xv[8]*c2;   // -> lane 10
            wacc[ch][5] += xv[4]*c8 - xv[8]*c4;   // -> lane 12
        }
    }

    // warp reductions: scalar part + gate dot (all-lanes result)
    #pragma unroll
    for (int o = 16; o; o >>= 1) {
        scal += __shfl_xor_sync(0xffffffffu, scal, o);
        gdot += __shfl_xor_sync(0xffffffffu, gdot, o);
    }

    const float gate = 1.f / (1.f + expf(-(gdot + __ldg(gate_b))));
    const float ss   = 1.f / (1.f + expf(-__ldg(sw_p)));
    const float sb   = 1.f / (1.f + expf(-__ldg(bw_p)));
    const float gsb  = gate * sb;

    // After this barrier no warp reads halo rows anymore -> safe to RMW own row.
    __syncthreads();
    #pragma unroll
    for (int ch = 0; ch < 2; ++ch) {
        const int c = lane + (ch << 5);
        {   // q0: deltas at blade 0 (chunk0/lane0 only) and blade 3
            float4 v = sm4[lr * ROW_F4 + swz(c, 0)];
            if (ch == 0 && lane == 0) v.x += gate * ss * scal;
            v.w += gsb * wacc[ch][0];
            sm4[lr * ROW_F4 + swz(c, 0)] = v;
        }
        {   // q1: deltas at blades 5, 6
            float4 v = sm4[lr * ROW_F4 + swz(c, 1)];
            v.y += gsb * wacc[ch][1];
            v.z += gsb * wacc[ch][2];
            sm4[lr * ROW_F4 + swz(c, 1)] = v;
        }
        {   // q2: deltas at blades 9, 10
            float4 v = sm4[lr * ROW_F4 + swz(c, 2)];
            v.y += gsb * wacc[ch][3];
            v.z += gsb * wacc[ch][4];
            sm4[lr * ROW_F4 + swz(c, 2)] = v;
        }
        {   // q3: delta at blade 12
            float4 v = sm4[lr * ROW_F4 + swz(c, 3)];
            v.x += gsb * wacc[ch][5];
            sm4[lr * ROW_F4 + swz(c, 3)] = v;
        }
    }
    __syncthreads();

    float4* og = (float4*)out + ((size_t)b * T_DIM + t0) * ROW_F4;
    #pragma unroll
    for (int it = 0; it < (TILE * ROW_F4) / THREADS; ++it) {
        int idx = it * THREADS + tid;
        int r = idx >> 8;
        int f = idx & 255;
        og[(size_t)r * ROW_F4 + f] = sm4[(r + HALO) * ROW_F4 + swz(f >> 2, f & 3)];
    }
}

extern "C" void kernel_launch(void* const* d_in, const int* in_sizes, int n_in,
                              void* d_out, int out_size)
{
    const float* x    = (const float*)d_in[0];
    const float* gw   = (const float*)d_in[1];
    const float* gb   = (const float*)d_in[2];
    const float* sw_p = (const float*)d_in[3];
    const float* bw_p = (const float*)d_in[4];
    float* out = (float*)d_out;

    const size_t smem = (size_t)ROWS * D_DIM * sizeof(float);  // 80 KB
    cudaFuncSetAttribute(clifford_kernel,
                         cudaFuncAttributeMaxDynamicSharedMemorySize, (int)smem);

    const int B = in_sizes[0] / (T_DIM * D_DIM);   // 8
    dim3 grid(T_DIM / TILE, B);
    clifford_kernel<<<grid, THREADS, smem>>>(x, gw, gb, sw_p, bw_p, out);
}

// round 11
// speedup vs baseline: 1.1504x; 1.1504x over previous
#include <cuda_runtime.h>

// CliffordInteractionExpert: B=8, T=4096, D=1024, ALG=16 (metric 3,1,0)
// Collapsed over shifts {1,2,4} via bilinearity:
//   S = x[t-1] + x[t-2] + x[t-4]
//   scal(t) = sum_D d_i * x_i * (3x_i - S_i)          (C0 diagonal)
//   wedge into blade i^j of each chunk: x_j*S_i - x_i*S_j,
//     (i,j) in {(1,2)->3,(1,4)->5,(2,4)->6,(1,8)->9,(2,8)->10,(4,8)->12}
//   out = x + gate*(sb*wedge spread + ss*scal at D-index 0)
//   gate = sigmoid(x . gate_w + gate_b)
//
// Layout: 128 threads per token; lane owns f4 positions f = g and g+128.
// 4-lane segment (g&~3) = one chunk (4 quads). Wedge cross-terms via
// width-4 shuffles. No shared-memory tile; shifted rows hit L1D/L2.

#define T_DIM 4096
#define D_F4 256              // float4 per 1024-float row
#define TOK_PER_BLK 4
#define THREADS (TOK_PER_BLK * 128)

__global__ void __launch_bounds__(THREADS, 3)
clifford_kernel(const float* __restrict__ x,
                const float* __restrict__ gate_w,
                const float* __restrict__ gate_b,
                const float* __restrict__ sw_p,
                const float* __restrict__ bw_p,
                float* __restrict__ out)
{
    __shared__ float2 red[TOK_PER_BLK][4];
    const int tid = threadIdx.x;
    const int tok = tid >> 7;          // token within block (0..3)
    const int g   = tid & 127;         // thread within token
    const int q   = g & 3;             // quad within chunk (same for both f positions)
    const int b   = blockIdx.y;
    const int t   = blockIdx.x * TOK_PER_BLK + tok;

    const float4* xb  = (const float4*)x + (size_t)b * T_DIM * D_F4;
    const float4* xr0 = xb + (size_t)t * D_F4;
    const float4* xr1 = xb + (size_t)((t - 1) & (T_DIM - 1)) * D_F4;
    const float4* xr2 = xb + (size_t)((t - 2) & (T_DIM - 1)) * D_F4;
    const float4* xr4 = xb + (size_t)((t - 4) & (T_DIM - 1)) * D_F4;

    // per-quad diagonal metric signs d[4q+j]:
    // q0:(+,+,+,-) q1:(+,-,-,-) q2:(-,+,+,+) q3:(+,+,+,-)
    const float sx  = (q == 2) ? -1.f : 1.f;
    const float syz = (q == 1) ? -1.f : 1.f;
    const float sw_ = (q == 2) ?  1.f : -1.f;

    float4 xv[2], dl[2];
    float scal = 0.f, gdot = 0.f;

    #pragma unroll
    for (int h = 0; h < 2; ++h) {
        const int f = g + (h << 7);
        const float4 xo = __ldg(xr0 + f);
        const float4 a1 = __ldg(xr1 + f);
        const float4 a2 = __ldg(xr2 + f);
        const float4 a4 = __ldg(xr4 + f);
        const float4 S  = make_float4(a1.x + a2.x + a4.x, a1.y + a2.y + a4.y,
                                      a1.z + a2.z + a4.z, a1.w + a2.w + a4.w);
        const float4 gw = __ldg((const float4*)gate_w + f);
        gdot += xo.x*gw.x + xo.y*gw.y + xo.z*gw.z + xo.w*gw.w;

        // scal contribution: d .* x .* (3x - S)
        scal += sx  * xo.x * (3.f*xo.x - S.x)
              + syz * (xo.y * (3.f*xo.y - S.y) + xo.z * (3.f*xo.z - S.z))
              + sw_ * xo.w * (3.f*xo.w - S.w);

        // broadcast vector-lane values within the 4-lane chunk segment
        const unsigned m = 0xffffffffu;
        const float x1b = __shfl_sync(m, xo.y, 0, 4);  // blade 1 (q0 .y)
        const float x2b = __shfl_sync(m, xo.z, 0, 4);  // blade 2 (q0 .z)
        const float S1b = __shfl_sync(m, S.y,  0, 4);
        const float S2b = __shfl_sync(m, S.z,  0, 4);
        const float x4b = __shfl_sync(m, xo.x, 1, 4);  // blade 4 (q1 .x)
        const float S4b = __shfl_sync(m, S.x,  1, 4);
        const float x8b = __shfl_sync(m, xo.x, 2, 4);  // blade 8 (q2 .x)
        const float S8b = __shfl_sync(m, S.x,  2, 4);

        const float w3  = x2b*S1b - x1b*S2b;   // blade 3  (q0 .w)
        const float w5  = x4b*S1b - x1b*S4b;   // blade 5  (q1 .y)
        const float w6  = x4b*S2b - x2b*S4b;   // blade 6  (q1 .z)
        const float w9  = x8b*S1b - x1b*S8b;   // blade 9  (q2 .y)
        const float w10 = x8b*S2b - x2b*S8b;   // blade 10 (q2 .z)
        const float w12 = x8b*S4b - x4b*S8b;   // blade 12 (q3 .x)

        float4 d;
        d.x = (q == 3) ? w12 : 0.f;
        d.y = (q == 1) ? w5  : (q == 2) ? w9  : 0.f;
        d.z = (q == 1) ? w6  : (q == 2) ? w10 : 0.f;
        d.w = (q == 0) ? w3  : 0.f;
        xv[h] = xo;
        dl[h] = d;
    }

    // reduce scal/gdot over the token's 128 threads
    #pragma unroll
    for (int o = 16; o; o >>= 1) {
        scal += __shfl_xor_sync(0xffffffffu, scal, o);
        gdot += __shfl_xor_sync(0xffffffffu, gdot, o);
    }
    if ((g & 31) == 0) red[tok][g >> 5] = make_float2(scal, gdot);
    __syncthreads();
    {
        const float2 r0 = red[tok][0], r1 = red[tok][1];
        const float2 r2 = red[tok][2], r3 = red[tok][3];
        scal = r0.x + r1.x + r2.x + r3.x;
        gdot = r0.y + r1.y + r2.y + r3.y;
    }

    const float gate = 1.f / (1.f + expf(-(gdot + __ldg(gate_b))));
    const float ss   = 1.f / (1.f + expf(-__ldg(sw_p)));
    const float sb   = 1.f / (1.f + expf(-__ldg(bw_p)));
    const float gsb  = gate * sb;

    float4* ob = (float4*)out + ((size_t)b * T_DIM + t) * D_F4;
    #pragma unroll
    for (int h = 0; h < 2; ++h) {
        const int f = g + (h << 7);
        float4 v = xv[h];
        v.x += gsb * dl[h].x;
        v.y += gsb * dl[h].y;
        v.z += gsb * dl[h].z;
        v.w += gsb * dl[h].w;
        if (f == 0) v.x += gate * ss * scal;   // D-index 0 scalar part
        ob[f] = v;
    }
}

extern "C" void kernel_launch(void* const* d_in, const int* in_sizes, int n_in,
                              void* d_out, int out_size)
{
    const float* x    = (const float*)d_in[0];
    const float* gw   = (const float*)d_in[1];
    const float* gb   = (const float*)d_in[2];
    const float* sw_p = (const float*)d_in[3];
    const float* bw_p = (const float*)d_in[4];
    float* out = (float*)d_out;

    const int B = in_sizes[0] / (T_DIM * D_F4 * 4);   // 8
    dim3 grid(T_DIM / TOK_PER_BLK, B);
    clifford_kernel<<<grid, THREADS>>>(x, gw, gb, sw_p, bw_p, out);
}